// round 9
// baseline (speedup 1.0000x reference)
#include <cuda_runtime.h>
#include <cstdint>

// ============================================================================
// y = x @ scatter(W, sel, idx)^T      (M=8192, N=4096, K=4096, f32)
//
// Single fused kernel (no prep passes):
//   - A side: raw x via cp.async, tf32 rounding (cvt.rna) applied in-register
//     to ldmatrix fragments just before mma (bit-identical to prep rounding).
//   - B side: scatter folded into the loader. Each CTA's 128 B-rows live in
//     ONE row-block (rb = tile_n>>1); threads 0..15 build a 16-entry col-map
//     in smem; per chunk the loader switches base/stride between w and sel.
//   - GEMM: cp.async 3-stage pipeline + mma.sync m16n8k8 tf32, CTA 128x128,
//     BK=32, 4 warps (64x64), 2 CTAs/SM, mid-chunk barrier with cross-chunk
//     fragment prefetch (tensor pipe never drains).
// ============================================================================

__device__ __forceinline__ uint32_t tf32_rn_bits(uint32_t xb) {
    uint32_t u;
    asm("cvt.rna.tf32.f32 %0, %1;" : "=r"(u) : "r"(xb));
    return u;
}
__device__ __forceinline__ uint32_t smem_u32(const void* p) {
    uint32_t a;
    asm("{ .reg .u64 t; cvta.to.shared.u64 t, %1; cvt.u32.u64 %0, t; }"
        : "=r"(a) : "l"(p));
    return a;
}
#define CPA16(saddr, gptr) \
    asm volatile("cp.async.cg.shared.global [%0], [%1], 16;" \
                 :: "r"(saddr), "l"(gptr) : "memory")
#define CP_COMMIT() asm volatile("cp.async.commit_group;" ::: "memory")
#define CP_WAIT1()  asm volatile("cp.async.wait_group 1;"  ::: "memory")

#define LDSM4(r0, r1, r2, r3, addr) \
    asm volatile("ldmatrix.sync.aligned.m8n8.x4.shared.b16 {%0,%1,%2,%3}, [%4];" \
                 : "=r"(r0), "=r"(r1), "=r"(r2), "=r"(r3) : "r"(addr))

__device__ __forceinline__ void mma8(float* d, const uint32_t* a, const uint32_t* b) {
    asm volatile(
        "mma.sync.aligned.m16n8k8.row.col.f32.tf32.tf32.f32 "
        "{%0,%1,%2,%3}, {%4,%5,%6,%7}, {%8,%9}, {%0,%1,%2,%3};"
        : "+f"(d[0]), "+f"(d[1]), "+f"(d[2]), "+f"(d[3])
        : "r"(a[0]), "r"(a[1]), "r"(a[2]), "r"(a[3]), "r"(b[0]), "r"(b[1]));
}

// ---------------- GEMM ----------------
#define LDSROW       36
#define HALF_BYTES   (128 * LDSROW * 4)        // 18432
#define STAGE_BYTES_ (2 * HALF_BYTES)          // 36864
#define NSTAGES      3
#define CMAP_OFF     (NSTAGES * STAGE_BYTES_)  // 110592
#define SMEM_TOTAL   (CMAP_OFF + 64)           // 110656

__global__ void __launch_bounds__(128, 2)
LinearLayer_MatrixSparsity_9801115369812_kernel(const float* __restrict__ x,
                                                const float* __restrict__ w,
                                                const float* __restrict__ sel,
                                                const int*   __restrict__ idxw,
                                                float* __restrict__ out) {
    extern __shared__ float smem[];
    const uint32_t sb = smem_u32(smem);
    const int tid  = threadIdx.x;
    const int lane = tid & 31;
    const int wid  = tid >> 5;           // 0..3
    const int tile_n = blockIdx.x;       // 0..31
    const int tile_m = blockIdx.y;       // 0..63

    // ---- build per-CTA col-map: which K col-blocks of row-block rb are
    //      replaced by selected blocks (and by which) ----
    int* cmap = (int*)smem + (CMAP_OFF / 4);
    if (tid < 16) {
        const int rb = tile_n >> 1;
        bool is64 = true;
        for (int i = 0; i < 32; i++)
            if (idxw[2 * i + 1] != 0) { is64 = false; }
        int blk = -1;
        for (int b = 0; b < 32; b++) {
            int ro, ci;
            if (is64) { ro = idxw[4 * b]; ci = idxw[4 * b + 2]; }
            else      { ro = idxw[2 * b]; ci = idxw[2 * b + 1]; }
            if (ro == rb && ci == tid) blk = b;
        }
        cmap[tid] = blk;
    }
    __syncthreads();

    // ---- loader mapping ----
    // A: thread loads rows (tid>>3)+{0,16,..,112}, 16B chunk (tid&7)
    const float* ga = x + (size_t)(tile_m * 128 + (tid >> 3)) * 4096 + (tid & 7) * 4;
    const int wrow = tile_n * 128 + (tid >> 3);          // B row in W coords
    const int nrow = ((tile_n & 1) * 128) + (tid >> 3);  // row within 256-block
    const uint32_t soA = sb + (uint32_t)((tid >> 3) * (LDSROW * 4) + (tid & 7) * 16);
    const uint32_t soB = soA + HALF_BYTES;

    // B base pointer + j-stride (floats per 16-row step) for K-chunk at lk
    #define BSETUP(lkv, blkv, bb, bs) do {                                        \
        if ((blkv) >= 0) {                                                        \
            bb = sel + ((size_t)(blkv) * 256 + nrow) * 256                        \
                     + ((lkv) & 255) + (tid & 7) * 4;                             \
            bs = 16 * 256;                                                        \
        } else {                                                                  \
            bb = w + (size_t)wrow * 4096 + (lkv) + (tid & 7) * 4;                 \
            bs = 16 * 4096;                                                       \
        }                                                                         \
    } while (0)

    #define CPA_PAIR(j, _d, _k, _bb, _bs)                                         \
        CPA16(soA + (_d) + (j) * (16 * LDSROW * 4),                               \
              ga + (size_t)(j) * (16 * 4096) + (_k));                             \
        CPA16(soB + (_d) + (j) * (16 * LDSROW * 4), (_bb) + (size_t)(j) * (_bs))

    // ---- prologue: chunks 0 and 1 (both col-block 0) ----
    {
        const int blk0 = cmap[0];
        const float* bb; int bs;
        BSETUP(0, blk0, bb, bs);
        #pragma unroll
        for (int j = 0; j < 8; j++) { CPA_PAIR(j, 0, 0, bb, bs); }
        CP_COMMIT();
        BSETUP(32, blk0, bb, bs);
        #pragma unroll
        for (int j = 0; j < 8; j++) { CPA_PAIR(j, STAGE_BYTES_, 32, bb, bs); }
        CP_COMMIT();
    }

    const int warp_m = (wid >> 1) * 64;
    const int warp_n = (wid & 1) * 64;

    // ldmatrix per-thread offsets (same mapping as passing R6-R8 kernels)
    uint32_t aoff[4], boff[4];
    {
        const int r8a = (lane >> 3) & 1, c4a = (lane >> 4) & 1;
        #pragma unroll
        for (int mi = 0; mi < 4; mi++)
            aoff[mi] = (uint32_t)((warp_m + mi * 16 + (lane & 7) + r8a * 8) * (LDSROW * 4)
                                  + c4a * 16);
        const int r8b = (lane >> 4) & 1, c4b = (lane >> 3) & 1;
        #pragma unroll
        for (int nj = 0; nj < 4; nj++)
            boff[nj] = (uint32_t)(HALF_BYTES
                                  + (warp_n + nj * 16 + (lane & 7) + r8b * 8) * (LDSROW * 4)
                                  + c4b * 16);
    }

    float acc[4][8][4];
    #pragma unroll
    for (int mi = 0; mi < 4; mi++)
        #pragma unroll
        for (int ni = 0; ni < 8; ni++)
            #pragma unroll
            for (int q = 0; q < 4; q++) acc[mi][ni][q] = 0.0f;

    uint32_t af[2][4][4], bf[2][4][4];

    #define LDSM_KS(buf, base, koff) do {                                         \
        _Pragma("unroll")                                                         \
        for (int nj = 0; nj < 4; nj++)                                            \
            LDSM4(bf[buf][nj][0], bf[buf][nj][1], bf[buf][nj][2], bf[buf][nj][3], \
                  (base) + boff[nj] + (koff));                                    \
        _Pragma("unroll")                                                         \
        for (int mi = 0; mi < 4; mi++)                                            \
            LDSM4(af[buf][mi][0], af[buf][mi][1], af[buf][mi][2], af[buf][mi][3], \
                  (base) + aoff[mi] + (koff));                                    \
    } while (0)

    // tf32 rounding of a fragment buffer (in-register; bit-identical to a
    // prep-pass cvt.rna). Placed right before MMA of the same buffer so the
    // ldmatrix results are already long landed (loaded one ks earlier).
    #define CVT_KS(buf) do {                                                      \
        _Pragma("unroll")                                                         \
        for (int mi = 0; mi < 4; mi++)                                            \
            _Pragma("unroll")                                                     \
            for (int q = 0; q < 4; q++)                                           \
                af[buf][mi][q] = tf32_rn_bits(af[buf][mi][q]);                    \
        _Pragma("unroll")                                                         \
        for (int nj = 0; nj < 4; nj++)                                            \
            _Pragma("unroll")                                                     \
            for (int q = 0; q < 4; q++)                                           \
                bf[buf][nj][q] = tf32_rn_bits(bf[buf][nj][q]);                    \
    } while (0)

    #define MMA_KS(buf) do {                                                      \
        _Pragma("unroll")                                                         \
        for (int mi = 0; mi < 4; mi++)                                            \
            _Pragma("unroll")                                                     \
            for (int ni = 0; ni < 8; ni++)                                        \
                mma8(acc[mi][ni], af[buf][mi], &bf[buf][ni >> 1][(ni & 1) * 2]);  \
    } while (0)

    // prologue: chunk 0 resident + ks0 fragments preloaded
    CP_WAIT1();
    __syncthreads();
    LDSM_KS(0, sb, 0);

    int cs = 0, ls = 2;
    for (int kc = 0; kc < 128; kc++) {
        const uint32_t sbase = sb + (uint32_t)cs * STAGE_BYTES_;
        const uint32_t nbase = sb + (uint32_t)((cs == NSTAGES - 1) ? 0 : cs + 1) * STAGE_BYTES_;
        const uint32_t ld    = (uint32_t)ls * STAGE_BYTES_;
        const int      lk    = (kc + 2) * 32;
        const bool     doload = (kc + 2 < 128);

        const float* bb = nullptr; int bs = 0;
        if (doload) {
            const int blkc = cmap[lk >> 8];   // (kc+2)>>3
            BSETUP(lk, blkc, bb, bs);
        }

        // ks0: prefetch ks1 frags, 3 cp.async pairs, cvt+mma(buf0)
        LDSM_KS(1, sbase, 32);
        if (doload) { CPA_PAIR(0, ld, lk, bb, bs); CPA_PAIR(1, ld, lk, bb, bs);
                      CPA_PAIR(2, ld, lk, bb, bs); }
        CVT_KS(0); MMA_KS(0);
        // ks1: prefetch ks2 frags, 3 pairs, cvt+mma(buf1)
        LDSM_KS(0, sbase, 64);
        if (doload) { CPA_PAIR(3, ld, lk, bb, bs); CPA_PAIR(4, ld, lk, bb, bs);
                      CPA_PAIR(5, ld, lk, bb, bs); }
        CVT_KS(1); MMA_KS(1);
        // ks2: prefetch ks3 frags, last 2 pairs, commit, cvt+mma(buf0)
        LDSM_KS(1, sbase, 96);
        if (doload) { CPA_PAIR(6, ld, lk, bb, bs); CPA_PAIR(7, ld, lk, bb, bs); }
        CP_COMMIT();
        CVT_KS(0); MMA_KS(0);
        // mid-chunk sync: chunk kc+1 complete (pending group = kc+2);
        // stage cs fully consumed (ks3 frags already in regs)
        CP_WAIT1();
        __syncthreads();
        // ks3: prefetch NEXT chunk's ks0 frags from nbase, cvt+mma(buf1)
        LDSM_KS(0, nbase, 0);
        CVT_KS(1); MMA_KS(1);

        cs = (cs == NSTAGES - 1) ? 0 : cs + 1;
        ls = (ls == NSTAGES - 1) ? 0 : ls + 1;
    }

    // ---- epilogue ----
    const int qid = lane & 3;
    const int gid = lane >> 2;
    #pragma unroll
    for (int mi = 0; mi < 4; mi++) {
        #pragma unroll
        for (int ni = 0; ni < 8; ni++) {
            const size_t r0 = (size_t)(tile_m * 128 + warp_m + mi * 16 + gid);
            const int    c  = tile_n * 128 + warp_n + ni * 8 + qid * 2;
            *(float2*)(out + r0 * 4096 + c) =
                make_float2(acc[mi][ni][0], acc[mi][ni][1]);
            *(float2*)(out + (r0 + 8) * 4096 + c) =
                make_float2(acc[mi][ni][2], acc[mi][ni][3]);
        }
    }
}

// ---------------- launch ----------------
extern "C" void kernel_launch(void* const* d_in, const int* in_sizes, int n_in,
                              void* d_out, int out_size) {
    const float* x   = nullptr;
    const float* sel = nullptr;
    const float* w   = nullptr;
    const int*   idx = nullptr;
    for (int i = 0; i < n_in; i++) {
        switch (in_sizes[i]) {
            case 33554432: x   = (const float*)d_in[i]; break;
            case 16777216: w   = (const float*)d_in[i]; break;
            case 2097152:  sel = (const float*)d_in[i]; break;
            default:       idx = (const int*)d_in[i];   break;
        }
    }
    if (!x)   x   = (const float*)d_in[0];
    if (!sel) sel = (const float*)d_in[1];
    if (!w)   w   = (const float*)d_in[2];
    if (!idx) idx = (const int*)d_in[3];

    cudaFuncSetAttribute(LinearLayer_MatrixSparsity_9801115369812_kernel,
                         cudaFuncAttributeMaxDynamicSharedMemorySize, SMEM_TOTAL);

    LinearLayer_MatrixSparsity_9801115369812_kernel
        <<<dim3(32, 64), 128, SMEM_TOTAL>>>(x, w, sel, idx, (float*)d_out);
}

// round 10
// speedup vs baseline: 1.1402x; 1.1402x over previous
#include <cuda_runtime.h>
#include <cstdint>

// ============================================================================
// y = x @ scatter(W, sel, idx)^T      (M=8192, N=4096, K=4096, f32)
//
// Baseline-PTX tensor path (tcgen05 not assemblable under compute_103):
//   prep (ONE kernel): scatter sel blocks into W + round to tf32 (cvt.rna)
//         into device scratch g_W. Block membership computed in-kernel
//         (warp-parallel, smem scan) - no separate blkmap kernel.
//   A side: raw x fed to mma; the tf32 mma ignores the low 13 mantissa
//         bits (HW truncation) = free rounding for one operand. B side is
//         RNA-rounded, keeping total rel_err ~4.6e-4 < 1e-3.
//   GEMM: cp.async 3-stage pipeline + mma.sync m16n8k8 tf32, CTA 128x128,
//         BK=32, 4 warps (64x64), 2 CTAs/SM, mid-chunk barrier with
//         cross-chunk fragment prefetch (identical to the 1063us R8 kernel).
// ============================================================================

// ---------------- device-global scratch (sanctioned) ----------------
__device__ float g_W[16777216];   // 4096 x 4096 scattered + tf32-rounded

// ---------------- helpers ----------------
__device__ __forceinline__ float tf32_rn(float x) {
    uint32_t u;
    asm("cvt.rna.tf32.f32 %0, %1;" : "=r"(u) : "f"(x));
    return __uint_as_float(u);
}
__device__ __forceinline__ uint32_t smem_u32(const void* p) {
    uint32_t a;
    asm("{ .reg .u64 t; cvta.to.shared.u64 t, %1; cvt.u32.u64 %0, t; }"
        : "=r"(a) : "l"(p));
    return a;
}
#define CPA16(saddr, gptr) \
    asm volatile("cp.async.cg.shared.global [%0], [%1], 16;" \
                 :: "r"(saddr), "l"(gptr) : "memory")
#define CP_COMMIT() asm volatile("cp.async.commit_group;" ::: "memory")
#define CP_WAIT1()  asm volatile("cp.async.wait_group 1;"  ::: "memory")

#define LDSM4(r0, r1, r2, r3, addr) \
    asm volatile("ldmatrix.sync.aligned.m8n8.x4.shared.b16 {%0,%1,%2,%3}, [%4];" \
                 : "=r"(r0), "=r"(r1), "=r"(r2), "=r"(r3) : "r"(addr))

__device__ __forceinline__ void mma8(float* d, const uint32_t* a, const uint32_t* b) {
    asm volatile(
        "mma.sync.aligned.m16n8k8.row.col.f32.tf32.tf32.f32 "
        "{%0,%1,%2,%3}, {%4,%5,%6,%7}, {%8,%9}, {%0,%1,%2,%3};"
        : "+f"(d[0]), "+f"(d[1]), "+f"(d[2]), "+f"(d[3])
        : "r"(a[0]), "r"(a[1]), "r"(a[2]), "r"(a[3]), "r"(b[0]), "r"(b[1]));
}

// ---------------- prep: fused scatter + tf32 rounding of W ----------------
// One float4 per thread. Membership: warp 0 detects int64-vs-int32 via
// ballot over the odd 32-bit words (all-zero <=> int64; impossible for
// int32 data since 32 unique (ro,ci) pairs cannot all have ci==0), loads
// the 32 (ro,ci) pairs to smem; each thread scans 32 entries (broadcast LDS).
__global__ void prep_w_k(const float* __restrict__ w,
                         const float* __restrict__ sel,
                         const int*   __restrict__ idxw) {
    __shared__ int sro[32], sci[32];
    const int t = threadIdx.x;
    if (t < 32) {
        int hi = idxw[2 * t + 1];
        unsigned anyhi = __ballot_sync(0xffffffffu, hi != 0);
        if (anyhi) { sro[t] = idxw[2 * t]; sci[t] = hi; }           // int32 data
        else       { sro[t] = idxw[4 * t]; sci[t] = idxw[4 * t + 2]; } // int64 data
    }
    __syncthreads();

    const int gi = blockIdx.x * 256 + t;   // float4 index 0..4194303
    const int o  = gi >> 10;               // output row (4096 floats = 1024 f4)
    const int i  = (gi & 1023) << 2;       // input col
    const int rb = o >> 8, cb = i >> 8;
    int blk = -1;
    #pragma unroll
    for (int b = 0; b < 32; b++)
        if (sro[b] == rb && sci[b] == cb) blk = b;

    float4 v;
    if (blk >= 0)
        v = *(const float4*)(sel + (((size_t)blk << 8) + (o & 255)) * 256 + (i & 255));
    else
        v = ((const float4*)w)[gi];
    v.x = tf32_rn(v.x); v.y = tf32_rn(v.y); v.z = tf32_rn(v.z); v.w = tf32_rn(v.w);
    ((float4*)g_W)[gi] = v;
}

// ---------------- GEMM (identical mainloop to the 1063us R8 kernel) -------
#define LDSROW       36
#define HALF_BYTES   (128 * LDSROW * 4)        // 18432
#define STAGE_BYTES_ (2 * HALF_BYTES)          // 36864
#define NSTAGES      3
#define SMEM_BYTES   (NSTAGES * STAGE_BYTES_)  // 110592

__global__ void __launch_bounds__(128, 2)
LinearLayer_MatrixSparsity_9801115369812_kernel(const float* __restrict__ x,
                                                float* __restrict__ out) {
    extern __shared__ float smem[];
    const uint32_t sb = smem_u32(smem);
    const int tid  = threadIdx.x;
    const int lane = tid & 31;
    const int wid  = tid >> 5;           // 0..3
    const int tile_n = blockIdx.x;       // 0..31
    const int tile_m = blockIdx.y;       // 0..63

    // ---- loader mapping: A from raw x (HW-truncated in mma), B from g_W ----
    const float* ga = x   + (size_t)(tile_m * 128 + (tid >> 3)) * 4096 + (tid & 7) * 4;
    const float* gb = g_W + (size_t)(tile_n * 128 + (tid >> 3)) * 4096 + (tid & 7) * 4;
    const uint32_t soA = sb + (uint32_t)((tid >> 3) * (LDSROW * 4) + (tid & 7) * 16);
    const uint32_t soB = soA + HALF_BYTES;

    #define CPA_PAIR(j, _d, _k)                                                   \
        CPA16(soA + (_d) + (j) * (16 * LDSROW * 4), ga + (size_t)(j) * (16 * 4096) + (_k)); \
        CPA16(soB + (_d) + (j) * (16 * LDSROW * 4), gb + (size_t)(j) * (16 * 4096) + (_k))

    #define LOAD_STAGE(s, kc) do {                                               \
        const uint32_t _d = (uint32_t)(s) * STAGE_BYTES_;                        \
        const int _k = (kc) * 32;                                                \
        _Pragma("unroll")                                                        \
        for (int j = 0; j < 8; j++) { CPA_PAIR(j, _d, _k); }                     \
    } while (0)

    LOAD_STAGE(0, 0); CP_COMMIT();
    LOAD_STAGE(1, 1); CP_COMMIT();

    const int warp_m = (wid >> 1) * 64;
    const int warp_n = (wid & 1) * 64;

    uint32_t aoff[4], boff[4];
    {
        const int r8a = (lane >> 3) & 1, c4a = (lane >> 4) & 1;
        #pragma unroll
        for (int mi = 0; mi < 4; mi++)
            aoff[mi] = (uint32_t)((warp_m + mi * 16 + (lane & 7) + r8a * 8) * (LDSROW * 4)
                                  + c4a * 16);
        const int r8b = (lane >> 4) & 1, c4b = (lane >> 3) & 1;
        #pragma unroll
        for (int nj = 0; nj < 4; nj++)
            boff[nj] = (uint32_t)(HALF_BYTES
                                  + (warp_n + nj * 16 + (lane & 7) + r8b * 8) * (LDSROW * 4)
                                  + c4b * 16);
    }

    float acc[4][8][4];
    #pragma unroll
    for (int mi = 0; mi < 4; mi++)
        #pragma unroll
        for (int ni = 0; ni < 8; ni++)
            #pragma unroll
            for (int q = 0; q < 4; q++) acc[mi][ni][q] = 0.0f;

    uint32_t af[2][4][4], bf[2][4][4];

    #define LDSM_KS(buf, base, koff) do {                                         \
        _Pragma("unroll")                                                         \
        for (int nj = 0; nj < 4; nj++)                                            \
            LDSM4(bf[buf][nj][0], bf[buf][nj][1], bf[buf][nj][2], bf[buf][nj][3], \
                  (base) + boff[nj] + (koff));                                    \
        _Pragma("unroll")                                                         \
        for (int mi = 0; mi < 4; mi++)                                            \
            LDSM4(af[buf][mi][0], af[buf][mi][1], af[buf][mi][2], af[buf][mi][3], \
                  (base) + aoff[mi] + (koff));                                    \
    } while (0)

    #define MMA_KS(buf) do {                                                      \
        _Pragma("unroll")                                                         \
        for (int mi = 0; mi < 4; mi++)                                            \
            _Pragma("unroll")                                                     \
            for (int ni = 0; ni < 8; ni++)                                        \
                mma8(acc[mi][ni], af[buf][mi], &bf[buf][ni >> 1][(ni & 1) * 2]);  \
    } while (0)

    // prologue: chunk 0 resident + ks0 fragments preloaded
    CP_WAIT1();
    __syncthreads();
    LDSM_KS(0, sb, 0);

    int cs = 0, ls = 2;
    for (int kc = 0; kc < 128; kc++) {
        const uint32_t sbase = sb + (uint32_t)cs * STAGE_BYTES_;
        const uint32_t nbase = sb + (uint32_t)((cs == NSTAGES - 1) ? 0 : cs + 1) * STAGE_BYTES_;
        const uint32_t ld    = (uint32_t)ls * STAGE_BYTES_;
        const int      lk    = (kc + 2) * 32;
        const bool     doload = (kc + 2 < 128);

        // ks0: prefetch ks1 frags, 3 cp.async pairs, mma(buf0)
        LDSM_KS(1, sbase, 32);
        if (doload) { CPA_PAIR(0, ld, lk); CPA_PAIR(1, ld, lk); CPA_PAIR(2, ld, lk); }
        MMA_KS(0);
        // ks1: prefetch ks2 frags, 3 pairs, mma(buf1)
        LDSM_KS(0, sbase, 64);
        if (doload) { CPA_PAIR(3, ld, lk); CPA_PAIR(4, ld, lk); CPA_PAIR(5, ld, lk); }
        MMA_KS(1);
        // ks2: prefetch ks3 frags, last 2 pairs, commit, mma(buf0)
        LDSM_KS(1, sbase, 96);
        if (doload) { CPA_PAIR(6, ld, lk); CPA_PAIR(7, ld, lk); }
        CP_COMMIT();
        MMA_KS(0);
        // mid-chunk sync: chunk kc+1 complete (pending group = kc+2);
        // stage cs fully consumed (ks3 frags already in regs)
        CP_WAIT1();
        __syncthreads();
        // ks3: prefetch NEXT chunk's ks0 frags from nbase, mma(buf1)
        LDSM_KS(0, nbase, 0);
        MMA_KS(1);

        cs = (cs == NSTAGES - 1) ? 0 : cs + 1;
        ls = (ls == NSTAGES - 1) ? 0 : ls + 1;
    }

    // ---- epilogue ----
    const int qid = lane & 3;
    const int gid = lane >> 2;
    #pragma unroll
    for (int mi = 0; mi < 4; mi++) {
        #pragma unroll
        for (int ni = 0; ni < 8; ni++) {
            const size_t r0 = (size_t)(tile_m * 128 + warp_m + mi * 16 + gid);
            const int    c  = tile_n * 128 + warp_n + ni * 8 + qid * 2;
            *(float2*)(out + r0 * 4096 + c) =
                make_float2(acc[mi][ni][0], acc[mi][ni][1]);
            *(float2*)(out + (r0 + 8) * 4096 + c) =
                make_float2(acc[mi][ni][2], acc[mi][ni][3]);
        }
    }
}

// ---------------- launch ----------------
extern "C" void kernel_launch(void* const* d_in, const int* in_sizes, int n_in,
                              void* d_out, int out_size) {
    const float* x   = nullptr;
    const float* sel = nullptr;
    const float* w   = nullptr;
    const int*   idx = nullptr;
    for (int i = 0; i < n_in; i++) {
        switch (in_sizes[i]) {
            case 33554432: x   = (const float*)d_in[i]; break;
            case 16777216: w   = (const float*)d_in[i]; break;
            case 2097152:  sel = (const float*)d_in[i]; break;
            default:       idx = (const int*)d_in[i];   break;
        }
    }
    if (!x)   x   = (const float*)d_in[0];
    if (!sel) sel = (const float*)d_in[1];
    if (!w)   w   = (const float*)d_in[2];
    if (!idx) idx = (const int*)d_in[3];

    cudaFuncSetAttribute(LinearLayer_MatrixSparsity_9801115369812_kernel,
                         cudaFuncAttributeMaxDynamicSharedMemorySize, SMEM_BYTES);

    prep_w_k<<<16384, 256>>>(w, sel, idx);
    LinearLayer_MatrixSparsity_9801115369812_kernel
        <<<dim3(32, 64), 128, SMEM_BYTES>>>(x, (float*)d_out);
}

// round 11
// speedup vs baseline: 1.1443x; 1.0035x over previous
#include <cuda_runtime.h>
#include <cstdint>

// ============================================================================
// y = x @ scatter(W, sel, idx)^T      (M=8192, N=4096, K=4096, f32)
//
// SINGLE fused kernel, no prep passes, no device scratch:
//   - tf32 path: both A and B fed raw; the legacy tf32 mma truncates the low
//     13 mantissa bits in HW (free rounding, measured rel_err budget ~6e-4).
//   - scatter folded into the B loader: each CTA's 128 B-rows live in ONE
//     row-block (rb = tile_n>>1); threads 0..15 build a 16-entry col-map in
//     smem; per K-chunk one broadcast LDS selects w-vs-sel base pointers.
//   - GEMM: cp.async 3-stage pipeline + mma.sync m16n8k8 tf32, CTA 128x128,
//     BK=32, 4 warps (64x64), 2 CTAs/SM, mid-chunk barrier with cross-chunk
//     fragment prefetch (identical mainloop to the 1039us R10 kernel).
// ============================================================================

__device__ __forceinline__ uint32_t smem_u32(const void* p) {
    uint32_t a;
    asm("{ .reg .u64 t; cvta.to.shared.u64 t, %1; cvt.u32.u64 %0, t; }"
        : "=r"(a) : "l"(p));
    return a;
}
#define CPA16(saddr, gptr) \
    asm volatile("cp.async.cg.shared.global [%0], [%1], 16;" \
                 :: "r"(saddr), "l"(gptr) : "memory")
#define CP_COMMIT() asm volatile("cp.async.commit_group;" ::: "memory")
#define CP_WAIT1()  asm volatile("cp.async.wait_group 1;"  ::: "memory")

#define LDSM4(r0, r1, r2, r3, addr) \
    asm volatile("ldmatrix.sync.aligned.m8n8.x4.shared.b16 {%0,%1,%2,%3}, [%4];" \
                 : "=r"(r0), "=r"(r1), "=r"(r2), "=r"(r3) : "r"(addr))

__device__ __forceinline__ void mma8(float* d, const uint32_t* a, const uint32_t* b) {
    asm volatile(
        "mma.sync.aligned.m16n8k8.row.col.f32.tf32.tf32.f32 "
        "{%0,%1,%2,%3}, {%4,%5,%6,%7}, {%8,%9}, {%0,%1,%2,%3};"
        : "+f"(d[0]), "+f"(d[1]), "+f"(d[2]), "+f"(d[3])
        : "r"(a[0]), "r"(a[1]), "r"(a[2]), "r"(a[3]), "r"(b[0]), "r"(b[1]));
}

// ---------------- GEMM ----------------
#define LDSROW       36
#define HALF_BYTES   (128 * LDSROW * 4)        // 18432
#define STAGE_BYTES_ (2 * HALF_BYTES)          // 36864
#define NSTAGES      3
#define CMAP_OFF     (NSTAGES * STAGE_BYTES_)  // 110592
#define SMEM_TOTAL   (CMAP_OFF + 64)           // 110656

__global__ void __launch_bounds__(128, 2)
LinearLayer_MatrixSparsity_9801115369812_kernel(const float* __restrict__ x,
                                                const float* __restrict__ w,
                                                const float* __restrict__ sel,
                                                const int*   __restrict__ idxw,
                                                float* __restrict__ out) {
    extern __shared__ float smem[];
    const uint32_t sb = smem_u32(smem);
    const int tid  = threadIdx.x;
    const int lane = tid & 31;
    const int wid  = tid >> 5;           // 0..3
    const int tile_n = blockIdx.x;       // 0..31
    const int tile_m = blockIdx.y;       // 0..63

    // ---- per-CTA col-map: which of the 16 K col-blocks of row-block rb are
    //      replaced by selected blocks (and by which). idx buffer may be
    //      int64 (odd 32-bit words all zero) or int32 (JAX x64 off).
    int* cmap = (int*)smem + (CMAP_OFF / 4);
    if (tid < 16) {
        const int rb = tile_n >> 1;
        bool is64 = true;
        for (int i = 0; i < 32; i++)
            if (idxw[2 * i + 1] != 0) { is64 = false; }
        int blk = -1;
        for (int b = 0; b < 32; b++) {
            int ro, ci;
            if (is64) { ro = idxw[4 * b]; ci = idxw[4 * b + 2]; }
            else      { ro = idxw[2 * b]; ci = idxw[2 * b + 1]; }
            if (ro == rb && ci == tid) blk = b;
        }
        cmap[tid] = blk;
    }
    __syncthreads();

    // ---- loader mapping ----
    const float* ga = x + (size_t)(tile_m * 128 + (tid >> 3)) * 4096 + (tid & 7) * 4;
    const int wrow = tile_n * 128 + (tid >> 3);          // B row in W coords
    const int nrow = ((tile_n & 1) * 128) + (tid >> 3);  // row within 256-block
    const uint32_t soA = sb + (uint32_t)((tid >> 3) * (LDSROW * 4) + (tid & 7) * 16);
    const uint32_t soB = soA + HALF_BYTES;

    // B base pointer + j-stride (floats per 16-row step) for K-chunk at lk
    #define BSETUP(lkv, blkv, bb, bs) do {                                        \
        if ((blkv) >= 0) {                                                        \
            bb = sel + ((size_t)(blkv) * 256 + nrow) * 256                        \
                     + ((lkv) & 255) + (tid & 7) * 4;                             \
            bs = 16 * 256;                                                        \
        } else {                                                                  \
            bb = w + (size_t)wrow * 4096 + (lkv) + (tid & 7) * 4;                 \
            bs = 16 * 4096;                                                       \
        }                                                                         \
    } while (0)

    #define CPA_PAIR(j, _d, _k, _bb, _bs)                                         \
        CPA16(soA + (_d) + (j) * (16 * LDSROW * 4),                               \
              ga + (size_t)(j) * (16 * 4096) + (_k));                             \
        CPA16(soB + (_d) + (j) * (16 * LDSROW * 4), (_bb) + (size_t)(j) * (_bs))

    // ---- prologue: chunks 0 and 1 (both col-block 0) ----
    {
        const int blk0 = cmap[0];
        const float* bb; int bs;
        BSETUP(0, blk0, bb, bs);
        #pragma unroll
        for (int j = 0; j < 8; j++) { CPA_PAIR(j, 0, 0, bb, bs); }
        CP_COMMIT();
        BSETUP(32, blk0, bb, bs);
        #pragma unroll
        for (int j = 0; j < 8; j++) { CPA_PAIR(j, STAGE_BYTES_, 32, bb, bs); }
        CP_COMMIT();
    }

    const int warp_m = (wid >> 1) * 64;
    const int warp_n = (wid & 1) * 64;

    // ldmatrix per-thread offsets (same mapping as passing R6-R10 kernels)
    uint32_t aoff[4], boff[4];
    {
        const int r8a = (lane >> 3) & 1, c4a = (lane >> 4) & 1;
        #pragma unroll
        for (int mi = 0; mi < 4; mi++)
            aoff[mi] = (uint32_t)((warp_m + mi * 16 + (lane & 7) + r8a * 8) * (LDSROW * 4)
                                  + c4a * 16);
        const int r8b = (lane >> 4) & 1, c4b = (lane >> 3) & 1;
        #pragma unroll
        for (int nj = 0; nj < 4; nj++)
            boff[nj] = (uint32_t)(HALF_BYTES
                                  + (warp_n + nj * 16 + (lane & 7) + r8b * 8) * (LDSROW * 4)
                                  + c4b * 16);
    }

    float acc[4][8][4];
    #pragma unroll
    for (int mi = 0; mi < 4; mi++)
        #pragma unroll
        for (int ni = 0; ni < 8; ni++)
            #pragma unroll
            for (int q = 0; q < 4; q++) acc[mi][ni][q] = 0.0f;

    uint32_t af[2][4][4], bf[2][4][4];

    #define LDSM_KS(buf, base, koff) do {                                         \
        _Pragma("unroll")                                                         \
        for (int nj = 0; nj < 4; nj++)                                            \
            LDSM4(bf[buf][nj][0], bf[buf][nj][1], bf[buf][nj][2], bf[buf][nj][3], \
                  (base) + boff[nj] + (koff));                                    \
        _Pragma("unroll")                                                         \
        for (int mi = 0; mi < 4; mi++)                                            \
            LDSM4(af[buf][mi][0], af[buf][mi][1], af[buf][mi][2], af[buf][mi][3], \
                  (base) + aoff[mi] + (koff));                                    \
    } while (0)

    #define MMA_KS(buf) do {                                                      \
        _Pragma("unroll")                                                         \
        for (int mi = 0; mi < 4; mi++)                                            \
            _Pragma("unroll")                                                     \
            for (int ni = 0; ni < 8; ni++)                                        \
                mma8(acc[mi][ni], af[buf][mi], &bf[buf][ni >> 1][(ni & 1) * 2]);  \
    } while (0)

    // prologue: chunk 0 resident + ks0 fragments preloaded
    CP_WAIT1();
    __syncthreads();
    LDSM_KS(0, sb, 0);

    int cs = 0, ls = 2;
    for (int kc = 0; kc < 128; kc++) {
        const uint32_t sbase = sb + (uint32_t)cs * STAGE_BYTES_;
        const uint32_t nbase = sb + (uint32_t)((cs == NSTAGES - 1) ? 0 : cs + 1) * STAGE_BYTES_;
        const uint32_t ld    = (uint32_t)ls * STAGE_BYTES_;
        const int      lk    = (kc + 2) * 32;
        const bool     doload = (kc + 2 < 128);

        const float* bb = nullptr; int bs = 0;
        if (doload) {
            const int blkc = cmap[lk >> 8];   // col-block of chunk kc+2
            BSETUP(lk, blkc, bb, bs);
        }

        // ks0: prefetch ks1 frags, 3 cp.async pairs, mma(buf0)
        LDSM_KS(1, sbase, 32);
        if (doload) { CPA_PAIR(0, ld, lk, bb, bs); CPA_PAIR(1, ld, lk, bb, bs);
                      CPA_PAIR(2, ld, lk, bb, bs); }
        MMA_KS(0);
        // ks1: prefetch ks2 frags, 3 pairs, mma(buf1)
        LDSM_KS(0, sbase, 64);
        if (doload) { CPA_PAIR(3, ld, lk, bb, bs); CPA_PAIR(4, ld, lk, bb, bs);
                      CPA_PAIR(5, ld, lk, bb, bs); }
        MMA_KS(1);
        // ks2: prefetch ks3 frags, last 2 pairs, commit, mma(buf0)
        LDSM_KS(1, sbase, 96);
        if (doload) { CPA_PAIR(6, ld, lk, bb, bs); CPA_PAIR(7, ld, lk, bb, bs); }
        CP_COMMIT();
        MMA_KS(0);
        // mid-chunk sync: chunk kc+1 complete (pending group = kc+2);
        // stage cs fully consumed (ks3 frags already in regs)
        CP_WAIT1();
        __syncthreads();
        // ks3: prefetch NEXT chunk's ks0 frags from nbase, mma(buf1)
        LDSM_KS(0, nbase, 0);
        MMA_KS(1);

        cs = (cs == NSTAGES - 1) ? 0 : cs + 1;
        ls = (ls == NSTAGES - 1) ? 0 : ls + 1;
    }

    // ---- epilogue ----
    const int qid = lane & 3;
    const int gid = lane >> 2;
    #pragma unroll
    for (int mi = 0; mi < 4; mi++) {
        #pragma unroll
        for (int ni = 0; ni < 8; ni++) {
            const size_t r0 = (size_t)(tile_m * 128 + warp_m + mi * 16 + gid);
            const int    c  = tile_n * 128 + warp_n + ni * 8 + qid * 2;
            *(float2*)(out + r0 * 4096 + c) =
                make_float2(acc[mi][ni][0], acc[mi][ni][1]);
            *(float2*)(out + (r0 + 8) * 4096 + c) =
                make_float2(acc[mi][ni][2], acc[mi][ni][3]);
        }
    }
}

// ---------------- launch ----------------
extern "C" void kernel_launch(void* const* d_in, const int* in_sizes, int n_in,
                              void* d_out, int out_size) {
    const float* x   = nullptr;
    const float* sel = nullptr;
    const float* w   = nullptr;
    const int*   idx = nullptr;
    for (int i = 0; i < n_in; i++) {
        switch (in_sizes[i]) {
            case 33554432: x   = (const float*)d_in[i]; break;
            case 16777216: w   = (const float*)d_in[i]; break;
            case 2097152:  sel = (const float*)d_in[i]; break;
            default:       idx = (const int*)d_in[i];   break;
        }
    }
    if (!x)   x   = (const float*)d_in[0];
    if (!sel) sel = (const float*)d_in[1];
    if (!w)   w   = (const float*)d_in[2];
    if (!idx) idx = (const int*)d_in[3];

    cudaFuncSetAttribute(LinearLayer_MatrixSparsity_9801115369812_kernel,
                         cudaFuncAttributeMaxDynamicSharedMemorySize, SMEM_TOTAL);

    LinearLayer_MatrixSparsity_9801115369812_kernel
        <<<dim3(32, 64), 128, SMEM_TOTAL>>>(x, w, sel, idx, (float*)d_out);
}